// round 4
// baseline (speedup 1.0000x reference)
#include <cuda_runtime.h>
#include <cstdint>

// Problem constants (fixed by the dataset)
#define PN0   200000
#define PN1   50000
#define PN2   10000
#define INF_  602
#define HID_  128
#define CLS_  41
#define FAN_  25

// GEMM tiling
#define KP_   608          // K padded to multiple of 32 (19 chunks)
#define MT_   64           // rows per block
#define KC_   32           // K chunk staged in smem
#define ASTR  68           // A smem row stride (conflict-free frag loads)
#define BSTR  136          // B smem row stride (conflict-free frag loads)

// Device scratch (no allocations allowed)
__device__ float g_W1t[KP_ * HID_];                 // W1 transposed [k][n], tf32-rounded
__device__ float g_h1[(size_t)PN1 * HID_];          // layer-1 activations (25.6 MB, L2-resident)
__device__ int   g_is64[2];                         // [0]=map1 is int64, [1]=neigh_idx is int64

__device__ __forceinline__ float tf32r(float x) {
    uint32_t u;
    asm("cvt.rna.tf32.f32 %0, %1;" : "=r"(u) : "f"(x));
    return __uint_as_float(u);
}

// ---------------------------------------------------------------------------
// Kernel 0: transpose+round W1 into [k][n]; detect index dtype widths.
// Grid: KP_ blocks x HID_ threads.
// ---------------------------------------------------------------------------
__global__ void setup_kernel(const float* __restrict__ W1,
                             const int* __restrict__ map1_w,
                             const int* __restrict__ neigh_w) {
    int k = blockIdx.x;
    int n = threadIdx.x;
    float v = 0.f;
    if (k < INF_) v = tf32r(W1[n * INF_ + k]);      // W1 is [HID_][INF_] row-major
    g_W1t[k * HID_ + n] = v;

    if (k == 0 && n == 0) {
        // If data is int64 (values < 2^31, nonneg), every odd 32-bit word is 0.
        // For int32 random indices the chance of 32 zeros is ~(1/2e5)^32.
        int f0 = 1, f1 = 1;
        for (int i = 1; i < 64; i += 2) {
            if (map1_w[i]  != 0) f0 = 0;
            if (neigh_w[i] != 0) f1 = 0;
        }
        g_is64[0] = f0;
        g_is64[1] = f1;
    }
}

// ---------------------------------------------------------------------------
// Kernel 1: h1[j] = relu(features[map1[j]] @ W1^T + b1), tf32 tensor cores.
// Block: 256 threads (8 warps), computes MT_=64 rows x 128 cols.
// Warp tile: m16 x n64 (8 n8 tiles), mma.sync.m16n8k8.tf32.
// ---------------------------------------------------------------------------
__global__ __launch_bounds__(256, 2) void h1_kernel(
    const float* __restrict__ feat,
    const float* __restrict__ bias1,
    const void*  __restrict__ map1_raw)
{
    __shared__ __align__(16) float As[MT_ * ASTR];
    __shared__ __align__(16) float Bs[KC_ * BSTR];
    __shared__ int   rows[MT_];
    __shared__ float b1s[HID_];

    int tid = threadIdx.x;
    int r0  = blockIdx.x * MT_;

    if (tid < MT_) {
        int j = r0 + tid;
        int g = -1;
        if (j < PN1) {
            if (g_is64[0]) g = (int)((const long long*)map1_raw)[j];
            else           g = ((const int*)map1_raw)[j];
        }
        rows[tid] = g;
    }
    if (tid < HID_) b1s[tid] = bias1[tid];
    __syncthreads();

    const int warp = tid >> 5;
    const int lane = tid & 31;
    const int grp  = lane >> 2;          // 0..7
    const int qid  = lane & 3;           // 0..3
    const int m0   = (warp >> 1) * 16;   // 0,16,32,48
    const int n0   = (warp & 1) * 64;    // 0,64

    float d[8][4];
    #pragma unroll
    for (int t = 0; t < 8; t++) {
        #pragma unroll
        for (int r = 0; r < 4; r++) d[t][r] = 0.f;
    }

    const int arow = tid >> 2;           // 0..63  (4 threads per A row)
    const int aq   = tid & 3;
    const int gi   = rows[arow];
    const float* fp = feat + (size_t)(gi < 0 ? 0 : gi) * INF_;

    for (int k0 = 0; k0 < KP_; k0 += KC_) {
        // ---- stage A: 64 rows x 32 k (gathered, tf32-rounded) ----
        #pragma unroll
        for (int i = 0; i < 4; i++) {
            int c2 = aq + 4 * i;                 // float2 index within row, 0..15
            int k  = k0 + 2 * c2;
            float2 v = make_float2(0.f, 0.f);
            if (gi >= 0 && k < INF_)             // INF_ even -> float2 never straddles
                v = *(const float2*)(fp + k);
            As[arow * ASTR + 2 * c2]     = tf32r(v.x);
            As[arow * ASTR + 2 * c2 + 1] = tf32r(v.y);
        }
        // ---- stage B: 32 k x 128 n (already rounded in g_W1t) ----
        #pragma unroll
        for (int i = 0; i < 4; i++) {
            int f4 = tid + 256 * i;              // float4 index 0..1023
            int e  = f4 * 4;
            int kk = e >> 7;                     // 0..31
            int nn = e & 127;
            float4 v = *(const float4*)&g_W1t[(k0 + kk) * HID_ + nn];
            *(float4*)&Bs[kk * BSTR + nn] = v;
        }
        __syncthreads();

        // ---- 4 k-steps of m16n8k8 tf32 mma ----
        #pragma unroll
        for (int ks = 0; ks < KC_; ks += 8) {
            uint32_t a0 = __float_as_uint(As[(m0 + grp)     * ASTR + ks + qid]);
            uint32_t a1 = __float_as_uint(As[(m0 + grp + 8) * ASTR + ks + qid]);
            uint32_t a2 = __float_as_uint(As[(m0 + grp)     * ASTR + ks + qid + 4]);
            uint32_t a3 = __float_as_uint(As[(m0 + grp + 8) * ASTR + ks + qid + 4]);
            #pragma unroll
            for (int t = 0; t < 8; t++) {
                uint32_t b0 = __float_as_uint(Bs[(ks + qid)     * BSTR + n0 + 8 * t + grp]);
                uint32_t b1 = __float_as_uint(Bs[(ks + qid + 4) * BSTR + n0 + 8 * t + grp]);
                asm volatile(
                    "mma.sync.aligned.m16n8k8.row.col.f32.tf32.tf32.f32 "
                    "{%0,%1,%2,%3}, {%4,%5,%6,%7}, {%8,%9}, {%0,%1,%2,%3};\n"
                    : "+f"(d[t][0]), "+f"(d[t][1]), "+f"(d[t][2]), "+f"(d[t][3])
                    : "r"(a0), "r"(a1), "r"(a2), "r"(a3), "r"(b0), "r"(b1));
            }
        }
        __syncthreads();
    }

    // ---- epilogue: bias + relu, write h1 ----
    const int row_a = r0 + m0 + grp;
    const int row_b = row_a + 8;
    #pragma unroll
    for (int t = 0; t < 8; t++) {
        int c0 = n0 + 8 * t + 2 * qid;
        int c1 = c0 + 1;
        if (row_a < PN1) {
            g_h1[(size_t)row_a * HID_ + c0] = fmaxf(d[t][0] + b1s[c0], 0.f);
            g_h1[(size_t)row_a * HID_ + c1] = fmaxf(d[t][1] + b1s[c1], 0.f);
        }
        if (row_b < PN1) {
            g_h1[(size_t)row_b * HID_ + c0] = fmaxf(d[t][2] + b1s[c0], 0.f);
            g_h1[(size_t)row_b * HID_ + c1] = fmaxf(d[t][3] + b1s[c1], 0.f);
        }
    }
}

// ---------------------------------------------------------------------------
// Kernel 2: agg[i] = mean_f h1[neigh_idx[i][f]]; out[i] = agg[i] @ W2^T + b2.
// One block (128 threads) per seed node. h1 is L2-resident (25.6 MB).
// ---------------------------------------------------------------------------
__global__ __launch_bounds__(128) void agg_kernel(
    const void*  __restrict__ neigh_raw,
    const float* __restrict__ W2,
    const float* __restrict__ b2,
    float*       __restrict__ out)
{
    __shared__ int   idx[FAN_];
    __shared__ float agg[HID_];

    const int i = blockIdx.x;
    const int t = threadIdx.x;

    if (t < FAN_) {
        long long v;
        if (g_is64[1]) v = ((const long long*)neigh_raw)[(size_t)i * FAN_ + t];
        else           v = (long long)((const int*)neigh_raw)[i * FAN_ + t];
        idx[t] = (int)v;
    }
    __syncthreads();

    float s = 0.f;
    #pragma unroll
    for (int f = 0; f < FAN_; f++)
        s += g_h1[(size_t)idx[f] * HID_ + t];
    agg[t] = s * (1.0f / (float)FAN_);
    __syncthreads();

    // Classification: warp w handles classes w, w+4, ... ; lane-strided dot + shfl reduce.
    const int w = t >> 5, l = t & 31;
    for (int c = w; c < CLS_; c += 4) {
        float p = 0.f;
        #pragma unroll
        for (int kk = 0; kk < 4; kk++)
            p += W2[c * HID_ + l + 32 * kk] * agg[l + 32 * kk];
        #pragma unroll
        for (int off = 16; off > 0; off >>= 1)
            p += __shfl_down_sync(0xffffffffu, p, off);
        if (l == 0) out[i * CLS_ + c] = p + b2[c];
    }
}

// ---------------------------------------------------------------------------
extern "C" void kernel_launch(void* const* d_in, const int* in_sizes, int n_in,
                              void* d_out, int out_size) {
    const float* feat  = (const float*)d_in[0];   // [200000, 602]
    const float* W1    = (const float*)d_in[1];   // [128, 602]
    const float* b1    = (const float*)d_in[2];   // [128]
    const float* W2    = (const float*)d_in[3];   // [41, 128]
    const float* b2    = (const float*)d_in[4];   // [41]
    const void*  map1  = d_in[5];                 // [50000] int32/int64 (runtime-detected)
    const void*  neigh = d_in[6];                 // [10000, 25] int32/int64
    float* out = (float*)d_out;                   // [10000, 41]

    setup_kernel<<<KP_, HID_>>>(W1, (const int*)map1, (const int*)neigh);
    h1_kernel<<<(PN1 + MT_ - 1) / MT_, 256>>>(feat, b1, map1);
    agg_kernel<<<PN2, 128>>>(neigh, W2, b2, out);
}

// round 7
// speedup vs baseline: 1.4987x; 1.4987x over previous
#include <cuda_runtime.h>
#include <cuda_fp16.h>
#include <cstdint>

// Problem constants (fixed by the dataset)
#define PN0   200000
#define PN1   50000
#define PN2   10000
#define INF_  602
#define HID_  128
#define CLS_  41
#define FAN_  25

// GEMM tiling (fp16 m16n8k16 path)
#define KP_    640         // K padded to multiple of 64 (10 chunks)
#define NCH_   10          // chunks
#define KCH_   64          // K per chunk staged in smem
#define MT_    64          // rows per block
#define ASTRH  72          // A smem row stride (halfs) -> conflict-free LDSM
#define BSTRH  136         // B smem row stride (halfs) -> conflict-free LDSM

// Device scratch (no allocations allowed). 16B-aligned for vector access.
__device__ __align__(16) __half    g_W1h[KP_ * HID_];              // W1^T [k][n], fp16
__device__ __align__(16) unsigned  g_h1h[(size_t)PN1 * (HID_/2)];  // h1 fp16 packed (12.8 MB)
__device__ int g_is64[2];                                          // [0]=map1 int64? [1]=neigh int64?

// ---------------------------------------------------------------------------
// Kernel 0: W1 [128][602] -> g_W1h [k][n] fp16, coalesced via smem transpose.
// Grid: 20 blocks (32 k each) x 256 threads. Also detects index dtype widths.
// ---------------------------------------------------------------------------
__global__ void setup_kernel(const float* __restrict__ W1,
                             const int* __restrict__ map1_w,
                             const int* __restrict__ neigh_w) {
    __shared__ __half s[32 * 130];
    const int t  = threadIdx.x;
    const int k0 = blockIdx.x * 32;

    // phase 1: coalesced read along k, store transposed tile s[kk][n]
    #pragma unroll
    for (int i = 0; i < 16; i++) {
        int idx = t + 256 * i;           // 4096 = 128 n x 32 kk
        int n   = idx >> 5;
        int kk  = idx & 31;
        int k   = k0 + kk;
        float v = (k < INF_) ? W1[n * INF_ + k] : 0.f;
        s[kk * 130 + n] = __float2half_rn(v);
    }
    __syncthreads();

    // phase 2: coalesced write along n (half2)
    #pragma unroll
    for (int i = 0; i < 8; i++) {
        int idx = t + 256 * i;           // 2048 = 32 kk x 64 half2
        int kk  = idx >> 6;
        int n2  = idx & 63;
        __half2 v = *(const __half2*)&s[kk * 130 + 2 * n2];
        *(__half2*)&g_W1h[(k0 + kk) * HID_ + 2 * n2] = v;
    }

    if (blockIdx.x == 0 && t == 0) {
        // int64 (values < 2^31, nonneg) => every odd 32-bit word is 0.
        int f0 = 1, f1 = 1;
        for (int i = 1; i < 64; i += 2) {
            if (map1_w[i]  != 0) f0 = 0;
            if (neigh_w[i] != 0) f1 = 0;
        }
        g_is64[0] = f0;
        g_is64[1] = f1;
    }
}

// ---------------------------------------------------------------------------
// Kernel 1: h1[j] = relu(features[map1[j]] @ W1^T + b1), fp16 tensor cores.
// Block: 256 threads (8 warps) -> 64 rows x 128 cols. Warp: m16 x n64.
// mma.sync.m16n8k16 fp16, ldmatrix fragment loads, register-prefetch
// double buffering. Feature gather uses float2 (row base is only 8B-aligned:
// 602*4 % 16 == 8, so float4 would trap on odd row indices).
// ---------------------------------------------------------------------------
__global__ __launch_bounds__(256, 2) void h1_kernel(
    const float* __restrict__ feat,
    const float* __restrict__ bias1,
    const void*  __restrict__ map1_raw)
{
    __shared__ __align__(16) __half As[MT_ * ASTRH];
    __shared__ __align__(16) __half Bs[KCH_ * BSTRH];
    __shared__ int   rows[MT_];
    __shared__ float b1s[HID_];

    const int tid = threadIdx.x;
    const int r0  = blockIdx.x * MT_;

    if (tid < MT_) {
        int j = r0 + tid;
        int g = -1;
        if (j < PN1) {
            if (g_is64[0]) g = (int)((const long long*)map1_raw)[j];
            else           g = ((const int*)map1_raw)[j];
        }
        rows[tid] = g;
    }
    if (tid < HID_) b1s[tid] = bias1[tid];
    __syncthreads();

    const int warp = tid >> 5;
    const int lane = tid & 31;
    const int grp  = lane >> 2;          // 0..7
    const int qid  = lane & 3;           // 0..3
    const int m0   = (warp >> 1) * 16;   // 0,16,32,48
    const int n0   = (warp & 1) * 64;    // 0,64

    float d[8][4];
    #pragma unroll
    for (int t = 0; t < 8; t++)
        #pragma unroll
        for (int r = 0; r < 4; r++) d[t][r] = 0.f;

    // A staging layout: 4 threads per row, thread covers 16 consecutive k.
    const int arow = tid >> 2;
    const int aq   = tid & 3;
    const int gi   = rows[arow];
    const float* fp = feat + (size_t)(gi < 0 ? 0 : gi) * INF_;

    // LDSM addresses (lane-dependent, chunk-invariant parts)
    const int a_r = m0 + (lane & 7) + 8 * ((lane >> 3) & 1);
    const int a_c = 8 * (lane >> 4);
    const uint32_t a_base = (uint32_t)__cvta_generic_to_shared(&As[a_r * ASTRH + a_c]);
    const int b_r = (lane & 7) + 8 * ((lane >> 3) & 1);
    const int b_c = n0 + 8 * (lane >> 4);
    const uint32_t b_base = (uint32_t)__cvta_generic_to_shared(&Bs[b_r * BSTRH + b_c]);

    float2 pa[8];                        // 16 k values, loaded as 8B (alignment-safe)
    uint4  pb[4];

    auto load_A = [&](int k0c) {
        #pragma unroll
        for (int i = 0; i < 8; i++) {
            int k = k0c + aq * 16 + 2 * i;   // even; INF_ even -> never straddles
            float2 v = make_float2(0.f, 0.f);
            if (gi >= 0 && k < INF_)
                v = *(const float2*)(fp + k);
            pa[i] = v;
        }
    };
    auto load_B = [&](int k0c) {
        #pragma unroll
        for (int i = 0; i < 4; i++) {
            int idx = tid + 256 * i;     // 1024 x 16B units
            int kk  = idx >> 4;
            int u   = idx & 15;
            pb[i] = *(const uint4*)&g_W1h[(k0c + kk) * HID_ + 8 * u];
        }
    };

    load_A(0);
    load_B(0);

    for (int c = 0; c < NCH_; c++) {
        // ---- stage A (fp16, 2x STS.128 per thread) ----
        {
            __half2 h[8];
            #pragma unroll
            for (int i = 0; i < 8; i++)
                h[i] = __floats2half2_rn(pa[i].x, pa[i].y);
            *(uint4*)&As[arow * ASTRH + aq * 16]     = *(uint4*)&h[0];
            *(uint4*)&As[arow * ASTRH + aq * 16 + 8] = *(uint4*)&h[4];
        }
        // ---- stage B ----
        #pragma unroll
        for (int i = 0; i < 4; i++) {
            int idx = tid + 256 * i;
            int kk  = idx >> 4;
            int u   = idx & 15;
            *(uint4*)&Bs[kk * BSTRH + 8 * u] = pb[i];
        }
        __syncthreads();

        // prefetch next chunk while MMAs run
        if (c + 1 < NCH_) {
            load_A((c + 1) * KCH_);
            load_B((c + 1) * KCH_);
        }

        // ---- 4 k16 steps ----
        #pragma unroll
        for (int ks = 0; ks < KCH_; ks += 16) {
            uint32_t a0, a1, a2, a3;
            asm volatile(
                "ldmatrix.sync.aligned.m8n8.x4.shared.b16 {%0,%1,%2,%3}, [%4];\n"
                : "=r"(a0), "=r"(a1), "=r"(a2), "=r"(a3)
                : "r"(a_base + (uint32_t)(ks * 2)));
            #pragma unroll
            for (int nb = 0; nb < 4; nb++) {
                uint32_t b0, b1, b2, b3;
                asm volatile(
                    "ldmatrix.sync.aligned.m8n8.x4.trans.shared.b16 {%0,%1,%2,%3}, [%4];\n"
                    : "=r"(b0), "=r"(b1), "=r"(b2), "=r"(b3)
                    : "r"(b_base + (uint32_t)((ks * BSTRH + 16 * nb) * 2)));
                int t0 = 2 * nb, t1 = 2 * nb + 1;
                asm volatile(
                    "mma.sync.aligned.m16n8k16.row.col.f32.f16.f16.f32 "
                    "{%0,%1,%2,%3}, {%4,%5,%6,%7}, {%8,%9}, {%0,%1,%2,%3};\n"
                    : "+f"(d[t0][0]), "+f"(d[t0][1]), "+f"(d[t0][2]), "+f"(d[t0][3])
                    : "r"(a0), "r"(a1), "r"(a2), "r"(a3), "r"(b0), "r"(b1));
                asm volatile(
                    "mma.sync.aligned.m16n8k16.row.col.f32.f16.f16.f32 "
                    "{%0,%1,%2,%3}, {%4,%5,%6,%7}, {%8,%9}, {%0,%1,%2,%3};\n"
                    : "+f"(d[t1][0]), "+f"(d[t1][1]), "+f"(d[t1][2]), "+f"(d[t1][3])
                    : "r"(a0), "r"(a1), "r"(a2), "r"(a3), "r"(b2), "r"(b3));
            }
        }
        __syncthreads();
    }

    // ---- epilogue: bias + relu, fp16 pack, write h1 ----
    const int row_a = r0 + m0 + grp;
    const int row_b = row_a + 8;
    #pragma unroll
    for (int t = 0; t < 8; t++) {
        int c0 = n0 + 8 * t + 2 * qid;      // even
        float bx = b1s[c0], by = b1s[c0 + 1];
        if (row_a < PN1) {
            __half2 v = __floats2half2_rn(fmaxf(d[t][0] + bx, 0.f),
                                          fmaxf(d[t][1] + by, 0.f));
            g_h1h[(size_t)row_a * (HID_/2) + (c0 >> 1)] = *(unsigned*)&v;
        }
        if (row_b < PN1) {
            __half2 v = __floats2half2_rn(fmaxf(d[t][2] + bx, 0.f),
                                          fmaxf(d[t][3] + by, 0.f));
            g_h1h[(size_t)row_b * (HID_/2) + (c0 >> 1)] = *(unsigned*)&v;
        }
    }
}

// ---------------------------------------------------------------------------
// Kernel 2: agg[i] = mean_f h1[neigh[i][f]]; out[i] = agg[i] @ W2^T + b2.
// One warp per seed (4 per block). h1 is fp16 and L2-resident.
// Lane l holds agg elements 4l..4l+3 (uint2 gather = 8B/lane, 256B/warp).
// ---------------------------------------------------------------------------
__global__ __launch_bounds__(128) void agg_kernel(
    const void*  __restrict__ neigh_raw,
    const float* __restrict__ W2,
    const float* __restrict__ b2,
    float*       __restrict__ out)
{
    __shared__ int idxs[4][32];
    const int w    = threadIdx.x >> 5;
    const int lane = threadIdx.x & 31;
    const int seed = blockIdx.x * 4 + w;

    if (lane < FAN_) {
        long long v;
        if (g_is64[1]) v = ((const long long*)neigh_raw)[(size_t)seed * FAN_ + lane];
        else           v = (long long)((const int*)neigh_raw)[seed * FAN_ + lane];
        idxs[w][lane] = (int)v;
    }
    __syncwarp();

    float a0 = 0.f, a1 = 0.f, a2 = 0.f, a3 = 0.f;
    #pragma unroll
    for (int f = 0; f < FAN_; f++) {
        int r = idxs[w][f];
        uint2 v = *(const uint2*)&g_h1h[(size_t)r * (HID_/2) + 2 * lane];
        __half2 lo = *(__half2*)&v.x;
        __half2 hi = *(__half2*)&v.y;
        float2 flo = __half22float2(lo);
        float2 fhi = __half22float2(hi);
        a0 += flo.x; a1 += flo.y; a2 += fhi.x; a3 += fhi.y;
    }

    const float inv = 1.0f / (float)FAN_;
    for (int c = 0; c < CLS_; c++) {
        float4 wv = *(const float4*)&W2[c * HID_ + 4 * lane];
        float p = wv.x * a0 + wv.y * a1 + wv.z * a2 + wv.w * a3;
        #pragma unroll
        for (int off = 16; off > 0; off >>= 1)
            p += __shfl_down_sync(0xffffffffu, p, off);
        if (lane == 0) out[seed * CLS_ + c] = p * inv + b2[c];
    }
}

// ---------------------------------------------------------------------------
extern "C" void kernel_launch(void* const* d_in, const int* in_sizes, int n_in,
                              void* d_out, int out_size) {
    const float* feat  = (const float*)d_in[0];   // [200000, 602]
    const float* W1    = (const float*)d_in[1];   // [128, 602]
    const float* b1    = (const float*)d_in[2];   // [128]
    const float* W2    = (const float*)d_in[3];   // [41, 128]
    const float* b2    = (const float*)d_in[4];   // [41]
    const void*  map1  = d_in[5];                 // [50000] int32/int64 (runtime-detected)
    const void*  neigh = d_in[6];                 // [10000, 25] int32/int64
    float* out = (float*)d_out;                   // [10000, 41]

    setup_kernel<<<KP_ / 32, 256>>>(W1, (const int*)map1, (const int*)neigh);
    h1_kernel<<<(PN1 + MT_ - 1) / MT_, 256>>>(feat, b1, map1);
    agg_kernel<<<PN2 / 4, 128>>>(neigh, W2, b2, out);
}

// round 9
// speedup vs baseline: 1.5219x; 1.0155x over previous
#include <cuda_runtime.h>
#include <cuda_fp16.h>
#include <cstdint>

// Problem constants (fixed by the dataset)
#define PN0   200000
#define PN1   50000
#define PN2   10000
#define INF_  602
#define HID_  128
#define CLS_  41
#define FAN_  25

// GEMM tiling (fp16 m16n8k16)
#define KP_    640         // K padded to multiple of 64 (10 chunks)
#define NCH_   10
#define KCH_   64
#define MT_    64          // rows per block
#define ASTRH  72          // A smem row stride (halfs): rows 4 banks apart -> conflict-free LDSM
#define BSTRH  72          // B smem row stride (halfs): rows = n, cols = k chunk

// Device scratch (no allocations allowed). 16B-aligned for vector access.
__device__ __align__(16) __half    g_W1h[HID_ * KP_];              // W1 [n][k] fp16, k padded
__device__ __align__(16) unsigned  g_h1h[(size_t)PN1 * (HID_/2)];  // h1 fp16 packed (12.8 MB)
__device__ int g_is64[2];                                          // [0]=map1 int64? [1]=neigh int64?

// ---------------------------------------------------------------------------
// Kernel 0: linear fp32->fp16 convert of W1 into padded [128][640] (same
// [n][k] layout, no transpose: mma.row.col's B operand IS k-major per n,
// which is W1's native layout). Fully coalesced. Also index-dtype sniff.
// Grid: 320 blocks x 256 threads (one half2 per thread).
// ---------------------------------------------------------------------------
__global__ void conv_kernel(const float* __restrict__ W1,
                            const int* __restrict__ map1_w,
                            const int* __restrict__ neigh_w) {
    int idx = blockIdx.x * 256 + threadIdx.x;   // 0..81919 = 128 n x 320 half2
    int n  = idx / (KP_ / 2);
    int k  = 2 * (idx % (KP_ / 2));
    __half2 h = __float2half2_rn(0.f);
    if (k < INF_) {                              // (n*602+k)*4 % 8 == 0 -> float2 safe
        float2 v = *(const float2*)&W1[n * INF_ + k];
        h = __floats2half2_rn(v.x, v.y);
    }
    *(__half2*)&g_W1h[n * KP_ + k] = h;

    if (idx == 0) {
        // int64 (values < 2^31, nonneg) => every odd 32-bit word is 0.
        int f0 = 1, f1 = 1;
        for (int i = 1; i < 64; i += 2) {
            if (map1_w[i]  != 0) f0 = 0;
            if (neigh_w[i] != 0) f1 = 0;
        }
        g_is64[0] = f0;
        g_is64[1] = f1;
    }
}

// ---------------------------------------------------------------------------
// Kernel 1: h1[j] = relu(features[map1[j]] @ W1^T + b1), fp16 tensor cores.
// 256 threads (8 warps) -> 64 rows x 128 cols; warp tile m16 x n64.
// Ping-pong smem buffers: ONE __syncthreads per K-chunk. Register prefetch
// of the next chunk's gathered A and B. ldmatrix x4 non-trans for both
// operands. Feature gather via float2 (row base only 8B-aligned:
// 602*4 % 16 == 8, float4 would trap on odd row indices).
// ---------------------------------------------------------------------------
__global__ __launch_bounds__(256, 2) void h1_kernel(
    const float* __restrict__ feat,
    const float* __restrict__ bias1,
    const void*  __restrict__ map1_raw)
{
    __shared__ __align__(16) __half As[2][MT_ * ASTRH];        // 2 x 9.0 KB
    __shared__ __align__(16) __half Bs[2][HID_ * BSTRH];       // 2 x 18.0 KB
    __shared__ int   rows[MT_];
    __shared__ float b1s[HID_];

    const int tid = threadIdx.x;
    const int r0  = blockIdx.x * MT_;

    if (tid < MT_) {
        int j = r0 + tid;
        int g = -1;
        if (j < PN1) {
            if (g_is64[0]) g = (int)((const long long*)map1_raw)[j];
            else           g = ((const int*)map1_raw)[j];
        }
        rows[tid] = g;
    }
    if (tid < HID_) b1s[tid] = bias1[tid];
    __syncthreads();

    const int warp = tid >> 5;
    const int lane = tid & 31;
    const int grp  = lane >> 2;          // 0..7
    const int qid  = lane & 3;           // 0..3
    const int m0   = (warp >> 1) * 16;   // 0,16,32,48
    const int n0   = (warp & 1) * 64;    // 0,64

    float d[8][4];
    #pragma unroll
    for (int t = 0; t < 8; t++)
        #pragma unroll
        for (int r = 0; r < 4; r++) d[t][r] = 0.f;

    // A staging: 4 threads per row, thread covers 16 consecutive k.
    const int arow = tid >> 2;
    const int aq   = tid & 3;
    const int gi   = rows[arow];
    const float* fp = feat + (size_t)(gi < 0 ? 0 : gi) * INF_;

    // LDSM lane-offsets (chunk-invariant).
    // A x4 matrices -> regs a0..a3 = m[0:8)k[0:8), m[8:16)k[0:8),
    //                               m[0:8)k[8:16), m[8:16)k[8:16).
    const int a_r = m0 + (lane & 7) + 8 * ((lane >> 3) & 1);
    const int a_c = 8 * (lane >> 4);
    // B x4 matrices (rows = n, cols = k) -> regs b0..b3 =
    //   n[0:8)k[0:8), n[0:8)k[8:16), n[8:16)k[0:8), n[8:16)k[8:16).
    const int b_row = n0 + (lane & 7) + 8 * ((lane >> 4) & 1);
    const int b_kof = 8 * ((lane >> 3) & 1);
    uint32_t a_base[2], b_base[2];
    #pragma unroll
    for (int p = 0; p < 2; p++) {
        a_base[p] = (uint32_t)__cvta_generic_to_shared(&As[p][a_r * ASTRH + a_c]);
        b_base[p] = (uint32_t)__cvta_generic_to_shared(&Bs[p][b_row * BSTRH + b_kof]);
    }

    float2 pa[8];
    uint4  pb[4];

    auto load_A = [&](int k0c) {
        #pragma unroll
        for (int i = 0; i < 8; i++) {
            int k = k0c + aq * 16 + 2 * i;       // even; never straddles (INF_ even)
            float2 v = make_float2(0.f, 0.f);
            if (gi >= 0 && k < INF_)
                v = *(const float2*)(fp + k);
            pa[i] = v;
        }
    };
    auto load_B = [&](int k0c) {
        #pragma unroll
        for (int i = 0; i < 4; i++) {
            int idx = tid + 256 * i;             // 1024 = 128 n x 8 uint4
            int n   = idx >> 3;
            int u   = idx & 7;
            pb[i] = *(const uint4*)&g_W1h[n * KP_ + k0c + 8 * u];
        }
    };
    auto store_AB = [&](int p) {
        __half2 h[8];
        #pragma unroll
        for (int i = 0; i < 8; i++)
            h[i] = __floats2half2_rn(pa[i].x, pa[i].y);
        *(uint4*)&As[p][arow * ASTRH + aq * 16]     = *(uint4*)&h[0];
        *(uint4*)&As[p][arow * ASTRH + aq * 16 + 8] = *(uint4*)&h[4];
        #pragma unroll
        for (int i = 0; i < 4; i++) {
            int idx = tid + 256 * i;
            int n   = idx >> 3;
            int u   = idx & 7;
            *(uint4*)&Bs[p][n * BSTRH + 8 * u] = pb[i];
        }
    };

    load_A(0);
    load_B(0);
    store_AB(0);

    for (int c = 0; c < NCH_; c++) {
        const int p = c & 1;
        if (c + 1 < NCH_) {
            load_A((c + 1) * KCH_);
            load_B((c + 1) * KCH_);
        }
        __syncthreads();     // buf p stores visible; also licenses store to buf p^1

        #pragma unroll
        for (int ks = 0; ks < KCH_; ks += 16) {
            uint32_t a0, a1, a2, a3;
            asm volatile(
                "ldmatrix.sync.aligned.m8n8.x4.shared.b16 {%0,%1,%2,%3}, [%4];\n"
                : "=r"(a0), "=r"(a1), "=r"(a2), "=r"(a3)
                : "r"(a_base[p] + (uint32_t)(ks * 2)));
            #pragma unroll
            for (int nb = 0; nb < 4; nb++) {
                uint32_t b0, b1, b2, b3;
                asm volatile(
                    "ldmatrix.sync.aligned.m8n8.x4.shared.b16 {%0,%1,%2,%3}, [%4];\n"
                    : "=r"(b0), "=r"(b1), "=r"(b2), "=r"(b3)
                    : "r"(b_base[p] + (uint32_t)((16 * nb * BSTRH + ks) * 2)));
                int t0 = 2 * nb, t1 = 2 * nb + 1;
                asm volatile(
                    "mma.sync.aligned.m16n8k16.row.col.f32.f16.f16.f32 "
                    "{%0,%1,%2,%3}, {%4,%5,%6,%7}, {%8,%9}, {%0,%1,%2,%3};\n"
                    : "+f"(d[t0][0]), "+f"(d[t0][1]), "+f"(d[t0][2]), "+f"(d[t0][3])
                    : "r"(a0), "r"(a1), "r"(a2), "r"(a3), "r"(b0), "r"(b1));
                asm volatile(
                    "mma.sync.aligned.m16n8k16.row.col.f32.f16.f16.f32 "
                    "{%0,%1,%2,%3}, {%4,%5,%6,%7}, {%8,%9}, {%0,%1,%2,%3};\n"
                    : "+f"(d[t1][0]), "+f"(d[t1][1]), "+f"(d[t1][2]), "+f"(d[t1][3])
                    : "r"(a0), "r"(a1), "r"(a2), "r"(a3), "r"(b2), "r"(b3));
            }
        }

        if (c + 1 < NCH_)
            store_AB(p ^ 1);     // other buffer; WAR vs chunk c-1 reads separated by this sync
    }

    // ---- epilogue: bias + relu, fp16 pack, write h1 ----
    const int row_a = r0 + m0 + grp;
    const int row_b = row_a + 8;
    #pragma unroll
    for (int t = 0; t < 8; t++) {
        int c0 = n0 + 8 * t + 2 * qid;      // even
        float bx = b1s[c0], by = b1s[c0 + 1];
        if (row_a < PN1) {
            __half2 v = __floats2half2_rn(fmaxf(d[t][0] + bx, 0.f),
                                          fmaxf(d[t][1] + by, 0.f));
            g_h1h[(size_t)row_a * (HID_/2) + (c0 >> 1)] = *(unsigned*)&v;
        }
        if (row_b < PN1) {
            __half2 v = __floats2half2_rn(fmaxf(d[t][2] + bx, 0.f),
                                          fmaxf(d[t][3] + by, 0.f));
            g_h1h[(size_t)row_b * (HID_/2) + (c0 >> 1)] = *(unsigned*)&v;
        }
    }
}

// ---------------------------------------------------------------------------
// Kernel 2: agg[i] = mean_f h1[neigh[i][f]]; out[i] = agg[i] @ W2^T + b2.
// One warp per seed (4 per block). h1 fp16, L2-resident.
// Lane l holds agg elements 4l..4l+3 (uint2 gather = 8B/lane, 256B/warp).
// ---------------------------------------------------------------------------
__global__ __launch_bounds__(128) void agg_kernel(
    const void*  __restrict__ neigh_raw,
    const float* __restrict__ W2,
    const float* __restrict__ b2,
    float*       __restrict__ out)
{
    __shared__ int idxs[4][32];
    const int w    = threadIdx.x >> 5;
    const int lane = threadIdx.x & 31;
    const int seed = blockIdx.x * 4 + w;

    if (lane < FAN_) {
        long long v;
        if (g_is64[1]) v = ((const long long*)neigh_raw)[(size_t)seed * FAN_ + lane];
        else           v = (long long)((const int*)neigh_raw)[seed * FAN_ + lane];
        idxs[w][lane] = (int)v;
    }
    __syncwarp();

    float a0 = 0.f, a1 = 0.f, a2 = 0.f, a3 = 0.f;
    #pragma unroll
    for (int f = 0; f < FAN_; f++) {
        int r = idxs[w][f];
        uint2 v = *(const uint2*)&g_h1h[(size_t)r * (HID_/2) + 2 * lane];
        __half2 lo = *(__half2*)&v.x;
        __half2 hi = *(__half2*)&v.y;
        float2 flo = __half22float2(lo);
        float2 fhi = __half22float2(hi);
        a0 += flo.x; a1 += flo.y; a2 += fhi.x; a3 += fhi.y;
    }

    const float inv = 1.0f / (float)FAN_;
    for (int c = 0; c < CLS_; c++) {
        float4 wv = *(const float4*)&W2[c * HID_ + 4 * lane];
        float p = wv.x * a0 + wv.y * a1 + wv.z * a2 + wv.w * a3;
        #pragma unroll
        for (int off = 16; off > 0; off >>= 1)
            p += __shfl_down_sync(0xffffffffu, p, off);
        if (lane == 0) out[seed * CLS_ + c] = p * inv + b2[c];
    }
}

// ---------------------------------------------------------------------------
extern "C" void kernel_launch(void* const* d_in, const int* in_sizes, int n_in,
                              void* d_out, int out_size) {
    const float* feat  = (const float*)d_in[0];   // [200000, 602]
    const float* W1    = (const float*)d_in[1];   // [128, 602]
    const float* b1    = (const float*)d_in[2];   // [128]
    const float* W2    = (const float*)d_in[3];   // [41, 128]
    const float* b2    = (const float*)d_in[4];   // [41]
    const void*  map1  = d_in[5];                 // [50000] int32/int64 (runtime-detected)
    const void*  neigh = d_in[6];                 // [10000, 25] int32/int64
    float* out = (float*)d_out;                   // [10000, 41]

    conv_kernel<<<(HID_ * KP_ / 2) / 256, 256>>>(W1, (const int*)map1, (const int*)neigh);
    h1_kernel<<<(PN1 + MT_ - 1) / MT_, 256>>>(feat, b1, map1);
    agg_kernel<<<PN2 / 4, 128>>>(neigh, W2, b2, out);
}

// round 10
// speedup vs baseline: 1.6739x; 1.0999x over previous
#include <cuda_runtime.h>
#include <cuda_fp16.h>
#include <cstdint>

// Problem constants (fixed by the dataset)
#define PN0   200000
#define PN1   50000
#define PN2   10000
#define INF_  602
#define HID_  128
#define CLS_  41
#define FAN_  25

// GEMM tiling (fp16 m16n8k16)
#define KP_    640         // K padded to multiple of 64 (10 chunks)
#define NCH_   10
#define KCH_   64
#define MT_    64          // rows per block
#define ASTRH  72          // A smem row stride (halfs): conflict-free LDSM
#define BSTRH  72          // B smem row stride (halfs): rows = n, cols = k chunk

// agg kernel smem strides (floats, pad kills bank conflicts; %4==0 for float4)
#define W2STR  132
#define AGSTR  132

// Device scratch (no allocations allowed). 16B-aligned for vector access.
__device__ __align__(16) __half    g_W1h[HID_ * KP_];              // W1 [n][k] fp16, k padded
__device__ __align__(16) unsigned  g_h1h[(size_t)PN1 * (HID_/2)];  // h1 fp16 packed (12.8 MB)
__device__ int g_is64[2];                                          // [0]=map1 int64? [1]=neigh int64?

// ---------------------------------------------------------------------------
// Kernel 0: linear fp32->fp16 convert of W1 into padded [128][640] ([n][k]
// layout — mma.row.col's B operand is k-major per n, W1's native layout).
// Fully coalesced. Also index-dtype sniff.
// ---------------------------------------------------------------------------
__global__ void conv_kernel(const float* __restrict__ W1,
                            const int* __restrict__ map1_w,
                            const int* __restrict__ neigh_w) {
    int idx = blockIdx.x * 256 + threadIdx.x;   // 0..81919 = 128 n x 320 half2
    int n  = idx / (KP_ / 2);
    int k  = 2 * (idx % (KP_ / 2));
    __half2 h = __float2half2_rn(0.f);
    if (k < INF_) {                              // (n*602+k)*4 % 8 == 0 -> float2 safe
        float2 v = *(const float2*)&W1[n * INF_ + k];
        h = __floats2half2_rn(v.x, v.y);
    }
    *(__half2*)&g_W1h[n * KP_ + k] = h;

    if (idx == 0) {
        // int64 (values < 2^31, nonneg) => every odd 32-bit word is 0.
        int f0 = 1, f1 = 1;
        for (int i = 1; i < 64; i += 2) {
            if (map1_w[i]  != 0) f0 = 0;
            if (neigh_w[i] != 0) f1 = 0;
        }
        g_is64[0] = f0;
        g_is64[1] = f1;
    }
}

// ---------------------------------------------------------------------------
// Kernel 1: h1[j] = relu(features[map1[j]] @ W1^T + b1), fp16 tensor cores.
// 256 threads (8 warps) -> 64 rows x 128 cols; warp tile m16 x n64.
// Ping-pong smem, ONE __syncthreads per K-chunk. B staged via cp.async.cg
// (no register staging, overlapped with the MMA loop); A gathered via float2
// LDG (feature row base only 8B-aligned: 602*4 % 16 == 8) into registers,
// converted, STS'd. launch_bounds(256,3) -> 24 warps/SM for latency hiding.
// ---------------------------------------------------------------------------
__global__ __launch_bounds__(256, 3) void h1_kernel(
    const float* __restrict__ feat,
    const float* __restrict__ bias1,
    const void*  __restrict__ map1_raw)
{
    __shared__ __align__(16) __half As[2][MT_ * ASTRH];        // 2 x 9.0 KB
    __shared__ __align__(16) __half Bs[2][HID_ * BSTRH];       // 2 x 18.0 KB
    __shared__ int   rows[MT_];
    __shared__ float b1s[HID_];

    const int tid = threadIdx.x;
    const int r0  = blockIdx.x * MT_;

    if (tid < MT_) {
        int j = r0 + tid;
        int g = -1;
        if (j < PN1) {
            if (g_is64[0]) g = (int)((const long long*)map1_raw)[j];
            else           g = ((const int*)map1_raw)[j];
        }
        rows[tid] = g;
    }
    if (tid < HID_) b1s[tid] = bias1[tid];
    __syncthreads();

    const int warp = tid >> 5;
    const int lane = tid & 31;
    const int grp  = lane >> 2;          // 0..7
    const int qid  = lane & 3;           // 0..3
    const int m0   = (warp >> 1) * 16;   // 0,16,32,48
    const int n0   = (warp & 1) * 64;    // 0,64

    float d[8][4];
    #pragma unroll
    for (int t = 0; t < 8; t++)
        #pragma unroll
        for (int r = 0; r < 4; r++) d[t][r] = 0.f;

    // A staging: 4 threads per row, thread covers 16 consecutive k.
    const int arow = tid >> 2;
    const int aq   = tid & 3;
    const int gi   = rows[arow];
    const float* fp = feat + (size_t)(gi < 0 ? 0 : gi) * INF_;

    // LDSM lane-offsets (chunk-invariant).
    const int a_r = m0 + (lane & 7) + 8 * ((lane >> 3) & 1);
    const int a_c = 8 * (lane >> 4);
    const int b_row = n0 + (lane & 7) + 8 * ((lane >> 4) & 1);
    const int b_kof = 8 * ((lane >> 3) & 1);
    uint32_t a_base[2], b_base[2];
    #pragma unroll
    for (int p = 0; p < 2; p++) {
        a_base[p] = (uint32_t)__cvta_generic_to_shared(&As[p][a_r * ASTRH + a_c]);
        b_base[p] = (uint32_t)__cvta_generic_to_shared(&Bs[p][b_row * BSTRH + b_kof]);
    }

    float2 pa[8];

    auto load_A = [&](int k0c) {
        #pragma unroll
        for (int i = 0; i < 8; i++) {
            int k = k0c + aq * 16 + 2 * i;       // even; never straddles (INF_ even)
            float2 v = make_float2(0.f, 0.f);
            if (gi >= 0 && k < INF_)
                v = *(const float2*)(fp + k);
            pa[i] = v;
        }
    };
    auto store_A = [&](int p) {
        __half2 h[8];
        #pragma unroll
        for (int i = 0; i < 8; i++)
            h[i] = __floats2half2_rn(pa[i].x, pa[i].y);
        *(uint4*)&As[p][arow * ASTRH + aq * 16]     = *(uint4*)&h[0];
        *(uint4*)&As[p][arow * ASTRH + aq * 16 + 8] = *(uint4*)&h[4];
    };
    auto copy_B = [&](int k0c, int p) {          // 4 x cp.async 16B per thread
        #pragma unroll
        for (int i = 0; i < 4; i++) {
            int idx = tid + 256 * i;             // 1024 = 128 n x 8 uint4
            int n   = idx >> 3;
            int u   = idx & 7;
            uint32_t dst = (uint32_t)__cvta_generic_to_shared(&Bs[p][n * BSTRH + 8 * u]);
            const __half* src = &g_W1h[n * KP_ + k0c + 8 * u];
            asm volatile("cp.async.cg.shared.global [%0], [%1], 16;\n"
                         :: "r"(dst), "l"(src) : "memory");
        }
        asm volatile("cp.async.commit_group;\n" ::: "memory");
    };

    // prologue: chunk 0 into buffer 0
    copy_B(0, 0);
    load_A(0);
    store_A(0);
    asm volatile("cp.async.wait_group 0;\n" ::: "memory");

    for (int c = 0; c < NCH_; c++) {
        const int p = c & 1;
        __syncthreads();                 // publish buf p; licenses writes to p^1
        if (c + 1 < NCH_) {
            copy_B((c + 1) * KCH_, p ^ 1);
            load_A((c + 1) * KCH_);
        }

        #pragma unroll
        for (int ks = 0; ks < KCH_; ks += 16) {
            uint32_t a0, a1, a2, a3;
            asm volatile(
                "ldmatrix.sync.aligned.m8n8.x4.shared.b16 {%0,%1,%2,%3}, [%4];\n"
                : "=r"(a0), "=r"(a1), "=r"(a2), "=r"(a3)
                : "r"(a_base[p] + (uint32_t)(ks * 2)));
            #pragma unroll
            for (int nb = 0; nb < 4; nb++) {
                uint32_t b0, b1, b2, b3;
                asm volatile(
                    "ldmatrix.sync.aligned.m8n8.x4.shared.b16 {%0,%1,%2,%3}, [%4];\n"
                    : "=r"(b0), "=r"(b1), "=r"(b2), "=r"(b3)
                    : "r"(b_base[p] + (uint32_t)((16 * nb * BSTRH + ks) * 2)));
                int t0 = 2 * nb, t1 = 2 * nb + 1;
                asm volatile(
                    "mma.sync.aligned.m16n8k16.row.col.f32.f16.f16.f32 "
                    "{%0,%1,%2,%3}, {%4,%5,%6,%7}, {%8,%9}, {%0,%1,%2,%3};\n"
                    : "+f"(d[t0][0]), "+f"(d[t0][1]), "+f"(d[t0][2]), "+f"(d[t0][3])
                    : "r"(a0), "r"(a1), "r"(a2), "r"(a3), "r"(b0), "r"(b1));
                asm volatile(
                    "mma.sync.aligned.m16n8k16.row.col.f32.f16.f16.f32 "
                    "{%0,%1,%2,%3}, {%4,%5,%6,%7}, {%8,%9}, {%0,%1,%2,%3};\n"
                    : "+f"(d[t1][0]), "+f"(d[t1][1]), "+f"(d[t1][2]), "+f"(d[t1][3])
                    : "r"(a0), "r"(a1), "r"(a2), "r"(a3), "r"(b2), "r"(b3));
            }
        }

        if (c + 1 < NCH_) {
            store_A(p ^ 1);              // WAR vs iter c-1 reads separated by sync above
            asm volatile("cp.async.wait_group 0;\n" ::: "memory");
        }
    }

    // ---- epilogue: bias + relu, fp16 pack, write h1 ----
    const int row_a = r0 + m0 + grp;
    const int row_b = row_a + 8;
    #pragma unroll
    for (int t = 0; t < 8; t++) {
        int c0 = n0 + 8 * t + 2 * qid;      // even
        float bx = b1s[c0], by = b1s[c0 + 1];
        if (row_a < PN1) {
            __half2 v = __floats2half2_rn(fmaxf(d[t][0] + bx, 0.f),
                                          fmaxf(d[t][1] + by, 0.f));
            g_h1h[(size_t)row_a * (HID_/2) + (c0 >> 1)] = *(unsigned*)&v;
        }
        if (row_b < PN1) {
            __half2 v = __floats2half2_rn(fmaxf(d[t][2] + bx, 0.f),
                                          fmaxf(d[t][3] + by, 0.f));
            g_h1h[(size_t)row_b * (HID_/2) + (c0 >> 1)] = *(unsigned*)&v;
        }
    }
}

// ---------------------------------------------------------------------------
// Kernel 2: agg + classify, shuffle-free.
// 256 threads, 8 seeds per block (grid 1250). Phase 1: warp w gathers and
// means seed w's neighbors (uint2 fp16 loads, h1 L2-resident) into smem.
// Phase 2: 328 (seed,class) outputs computed thread-per-output as float4
// dot products from smem (W2 staged once, stride-132 pad = conflict-free).
// ---------------------------------------------------------------------------
__global__ __launch_bounds__(256) void agg_kernel(
    const void*  __restrict__ neigh_raw,
    const float* __restrict__ W2,
    const float* __restrict__ b2,
    float*       __restrict__ out)
{
    __shared__ float W2s[CLS_ * W2STR];      // 21.2 KB
    __shared__ float aggS[8 * AGSTR];        // 4.2 KB
    __shared__ float b2s[CLS_];
    __shared__ int   idxs[8][32];

    const int t    = threadIdx.x;
    const int w    = t >> 5;
    const int lane = t & 31;
    const int seed0 = blockIdx.x * 8;

    // stage W2 / b2
    for (int i = t; i < CLS_ * HID_; i += 256) {
        int c = i >> 7, k = i & 127;
        W2s[c * W2STR + k] = W2[i];
    }
    if (t < CLS_) b2s[t] = b2[t];

    // neighbor indices (warp w -> seed w)
    if (lane < FAN_) {
        long long v;
        if (g_is64[1]) v = ((const long long*)neigh_raw)[(size_t)(seed0 + w) * FAN_ + lane];
        else           v = (long long)((const int*)neigh_raw)[(seed0 + w) * FAN_ + lane];
        idxs[w][lane] = (int)v;
    }
    __syncwarp();

    // gather + mean: lane l owns elements 4l..4l+3
    float a0 = 0.f, a1 = 0.f, a2 = 0.f, a3 = 0.f;
    #pragma unroll
    for (int f = 0; f < FAN_; f++) {
        int r = idxs[w][f];
        uint2 v = *(const uint2*)&g_h1h[(size_t)r * (HID_/2) + 2 * lane];
        float2 flo = __half22float2(*(__half2*)&v.x);
        float2 fhi = __half22float2(*(__half2*)&v.y);
        a0 += flo.x; a1 += flo.y; a2 += fhi.x; a3 += fhi.y;
    }
    const float inv = 1.0f / (float)FAN_;
    *(float4*)&aggS[w * AGSTR + 4 * lane] =
        make_float4(a0 * inv, a1 * inv, a2 * inv, a3 * inv);
    __syncthreads();

    // 328 outputs, thread-per-(seed,class), float4 dots (no shuffles)
    for (int o = t; o < 8 * CLS_; o += 256) {
        int s = o / CLS_;
        int c = o - s * CLS_;
        const float4* wr = (const float4*)&W2s[c * W2STR];
        const float4* ar = (const float4*)&aggS[s * AGSTR];
        float acc = 0.f;
        #pragma unroll
        for (int k = 0; k < HID_ / 4; k++) {
            float4 wv = wr[k];
            float4 av = ar[k];
            acc += wv.x * av.x + wv.y * av.y + wv.z * av.z + wv.w * av.w;
        }
        out[(seed0 + s) * CLS_ + c] = acc + b2s[c];
    }
}

// ---------------------------------------------------------------------------
extern "C" void kernel_launch(void* const* d_in, const int* in_sizes, int n_in,
                              void* d_out, int out_size) {
    const float* feat  = (const float*)d_in[0];   // [200000, 602]
    const float* W1    = (const float*)d_in[1];   // [128, 602]
    const float* b1    = (const float*)d_in[2];   // [128]
    const float* W2    = (const float*)d_in[3];   // [41, 128]
    const float* b2    = (const float*)d_in[4];   // [41]
    const void*  map1  = d_in[5];                 // [50000] int32/int64 (runtime-detected)
    const void*  neigh = d_in[6];                 // [10000, 25] int32/int64
    float* out = (float*)d_out;                   // [10000, 41]

    conv_kernel<<<(HID_ * KP_ / 2) / 256, 256>>>(W1, (const int*)map1, (const int*)neigh);
    h1_kernel<<<(PN1 + MT_ - 1) / MT_, 256>>>(feat, b1, map1);
    agg_kernel<<<PN2 / 8, 256>>>(neigh, W2, b2, out);
}